// round 2
// baseline (speedup 1.0000x reference)
#include <cuda_runtime.h>
#include <cuda_bf16.h>

// SpatialTransformer: B=16, H=W=384, C=32, fp32, NHWC.
// Bitwise-faithful fp32 replication of the JAX reference chain (IEEE intrinsics,
// LAPACK-flavored 2x2 inverse) + fused bilinear sample.
// 8 threads per output pixel, one float4 (4 channels) each.

#define B_ 16
#define H_ 384
#define W_ 384
#define C_ 32
#define CV_ (C_/4)   // float4 groups per pixel = 8

__device__ float g_coef[B_][8];   // m00, m01, cy, m10, m11, cx

// ---- per-batch theta adjustment: mimic jnp.linalg.inv (sgetrf+strsm) exactly ----
__global__ void st_setup_kernel(const float* __restrict__ theta)
{
    int b = threadIdx.x;
    if (b >= B_) return;
    const float* t = theta + b * 6;
    float a00 = t[0], a01 = t[1], a02 = t[2];
    float a10 = t[3], a11 = t[4], a12 = t[5];

    // sgetf2 pivot: isamax over column 0 (strict > picks row 2)
    bool piv = fabsf(a10) > fabsf(a00);
    float b00 = piv ? a10 : a00;   // row-swapped A'
    float b01 = piv ? a11 : a01;
    float b10 = piv ? a00 : a10;
    float b11 = piv ? a01 : a11;

    // sgetf2: scale by reciprocal (sscal with 1/pivot), then sger (mul+sub, no fma)
    float r   = __frcp_rn(b00);                       // RN(1/b00)
    float l   = __fmul_rn(b10, r);                    // L21
    float u11 = __fsub_rn(b11, __fmul_rn(l, b01));    // U22

    // strsm: X = U^{-1} L^{-1} I  (true divisions)
    float x10 = __fdiv_rn(-l, u11);
    float x00 = __fdiv_rn(__fsub_rn(1.0f, __fmul_rn(x10, b01)), b00);
    float x11 = __fdiv_rn(1.0f, u11);
    float x01 = __fdiv_rn(-__fmul_rn(x11, b01), b00);

    // undo pivot: A^{-1} = X * P (swap columns)
    float m00 = piv ? x01 : x00;
    float m01 = piv ? x00 : x01;
    float m10 = piv ? x11 : x10;
    float m11 = piv ? x10 : x11;

    // x_center = (-a02 + 0.5)*m00 ; y_center = (-a12 + 0.5)*m11
    float xc = __fmul_rn(__fadd_rn(-a02, 0.5f), m00);
    float yc = __fmul_rn(__fadd_rn(-a12, 0.5f), m11);
    float cy = __fsub_rn(__fmul_rn(yc, 2.0f), 1.0f);  // row-0 translation
    float cx = __fsub_rn(__fmul_rn(xc, 2.0f), 1.0f);  // row-1 translation

    g_coef[b][0] = m00; g_coef[b][1] = m01; g_coef[b][2] = cy;
    g_coef[b][3] = m10; g_coef[b][4] = m11; g_coef[b][5] = cx;
}

__global__ __launch_bounds__(256)
void st_bilinear_kernel(const float4* __restrict__ img,
                        float4* __restrict__ out)
{
    int tid = blockIdx.x * blockDim.x + threadIdx.x;
    const int PIX = B_ * H_ * W_;
    int pix = tid >> 3;          // output pixel index
    int cg  = tid & 7;           // channel group (float4)
    if (pix >= PIX) return;

    int b   = pix / (H_ * W_);
    int rem = pix - b * (H_ * W_);
    int i   = rem / W_;          // row
    int j   = rem - i * W_;      // col

    float m00 = g_coef[b][0], m01 = g_coef[b][1], cy = g_coef[b][2];
    float m10 = g_coef[b][3], m11 = g_coef[b][4], cx = g_coef[b][5];

    // linspace: iota*step + start  (separate RN mul / RN add)
    const float STEP = 2.0f / 383.0f;
    float xs = __fadd_rn(__fmul_rn((float)j, STEP), -1.0f);
    float ys = __fadd_rn(__fmul_rn((float)i, STEP), -1.0f);

    // einsum: ascending-k fma chain, last term (+cy*1) is a plain RN add
    float gx = __fadd_rn(__fmaf_rn(m01, ys, __fmul_rn(m00, xs)), cy);
    float gy = __fadd_rn(__fmaf_rn(m11, ys, __fmul_rn(m10, xs)), cx);

    // x = ((g+1)*W)*0.5  (left-assoc as in python)
    float x = __fmul_rn(__fmul_rn(__fadd_rn(gx, 1.0f), 384.0f), 0.5f);
    float y = __fmul_rn(__fmul_rn(__fadd_rn(gy, 1.0f), 384.0f), 0.5f);

    int x0 = (int)floorf(x);
    int y0 = (int)floorf(y);
    int x1 = x0 + 1;
    int y1 = y0 + 1;
    x0 = min(max(x0, 0), W_ - 1);
    x1 = min(max(x1, 0), W_ - 1);
    y0 = min(max(y0, 0), H_ - 1);
    y1 = min(max(y1, 0), H_ - 1);
    float x0f = (float)x0, x1f = (float)x1;
    float y0f = (float)y0, y1f = (float)y1;

    float wxa = __fsub_rn(x1f, x);   // (x1f - x)
    float wxc = __fsub_rn(x, x0f);   // (x - x0f)
    float wya = __fsub_rn(y1f, y);   // (y1f - y)
    float wyb = __fsub_rn(y, y0f);   // (y - y0f)
    float wa = __fmul_rn(wxa, wya);
    float wb = __fmul_rn(wxa, wyb);
    float wc = __fmul_rn(wxc, wya);
    float wd = __fmul_rn(wxc, wyb);

    int base = b * (H_ * W_ * CV_);
    float4 ga = __ldg(img + base + (y0 * W_ + x0) * CV_ + cg);
    float4 gb = __ldg(img + base + (y1 * W_ + x0) * CV_ + cg);
    float4 gc = __ldg(img + base + (y0 * W_ + x1) * CV_ + cg);
    float4 gd = __ldg(img + base + (y1 * W_ + x1) * CV_ + cg);

    // wa*ga + wb*gb + wc*gc + wd*gd  (left-assoc, separate RN mul/add)
    float4 r;
    r.x = __fadd_rn(__fadd_rn(__fadd_rn(__fmul_rn(wa, ga.x), __fmul_rn(wb, gb.x)),
                               __fmul_rn(wc, gc.x)), __fmul_rn(wd, gd.x));
    r.y = __fadd_rn(__fadd_rn(__fadd_rn(__fmul_rn(wa, ga.y), __fmul_rn(wb, gb.y)),
                               __fmul_rn(wc, gc.y)), __fmul_rn(wd, gd.y));
    r.z = __fadd_rn(__fadd_rn(__fadd_rn(__fmul_rn(wa, ga.z), __fmul_rn(wb, gb.z)),
                               __fmul_rn(wc, gc.z)), __fmul_rn(wd, gd.z));
    r.w = __fadd_rn(__fadd_rn(__fadd_rn(__fmul_rn(wa, ga.w), __fmul_rn(wb, gb.w)),
                               __fmul_rn(wc, gc.w)), __fmul_rn(wd, gd.w));

    out[base + (i * W_ + j) * CV_ + cg] = r;
}

extern "C" void kernel_launch(void* const* d_in, const int* in_sizes, int n_in,
                              void* d_out, int out_size)
{
    const float4* img   = (const float4*)d_in[0];   // images: (16,384,384,32) f32
    const float*  theta = (const float*)d_in[1];    // theta:  (16,6) f32
    float4* out = (float4*)d_out;

    st_setup_kernel<<<1, 32>>>(theta);

    const int total = B_ * H_ * W_ * 8;             // 8 threads per pixel
    const int threads = 256;
    const int blocks = (total + threads - 1) / threads;
    st_bilinear_kernel<<<blocks, threads>>>(img, out);
}